// round 3
// baseline (speedup 1.0000x reference)
#include <cuda_runtime.h>

#define H 1024
#define W 2048
#define B 8
#define N 64
#define NTASK (B * N)      // 512
#define THREADS 1024
#define NWARP (THREADS / 32)

// Single block, single launch. 32 warps handle 512 (batch, fixation) tasks.
// fm is zero outside fixation windows, so the dot product only needs covered
// columns. Per task (b, i) owning row y = ys[b][i] (only if i is the first
// fixation in batch b hitting y):
//   - cnt==1 (common): enumerate the kw-column window directly
//   - cnt>1 (rare):   full-width replay over matched fixations in scan order
//   - pole row:       entire row is 1.0 -> vectorized row sum
// Block-wide reduction at the end; thread 0 writes the scaled scalar.
__global__ void __launch_bounds__(THREADS)
spherical_nss_kernel(const float* __restrict__ y_pred,
                     const float* __restrict__ fixations,
                     const float* __restrict__ edge_vals,
                     const int*   __restrict__ ker_ws,
                     float* __restrict__ d_out) {
    const int tid  = threadIdx.x;
    const int l    = tid & 31;
    const int warp = tid >> 5;

    __shared__ int sxs[NTASK];
    __shared__ int sys[NTASK];
    __shared__ float swarp[NWARP];

    // Load + round all 512 fixations once (rintf == jnp.rint, half-to-even).
    if (tid < NTASK) {
        float2 f = ((const float2*)fixations)[tid];
        sxs[tid] = (int)rintf(f.x * (float)(W - 1));
        sys[tid] = (int)rintf(f.y * (float)(H - 1));
    }
    __syncthreads();

    float acc = 0.0f;

    // Each warp processes tasks warp, warp+32, ... (16 tasks).
    for (int t = warp; t < NTASK; t += NWARP) {
        const int b = t >> 6;
        const int i = t & 63;
        const int base = b * N;
        const int y = sys[base + i];

        // 64-bit mask of fixations in batch b hitting row y.
        unsigned lo = __ballot_sync(0xffffffffu, sys[base + l] == y);
        unsigned hi = __ballot_sync(0xffffffffu, sys[base + l + 32] == y);
        unsigned long long mask =
            ((unsigned long long)hi << 32) | (unsigned long long)lo;

        // Dedup: only the first fixation index with this row processes it.
        if (i > 0 && (mask & ((1ull << i) - 1ull))) continue;

        const float* row = y_pred + ((size_t)b * H + y) * W;

        if (y == 0 || y == H - 1) {
            // Pole: whole row forced to 1.0
            const float4* row4 = (const float4*)row;
            #pragma unroll 4
            for (int c = l; c < W / 4; c += 32) {
                float4 v = row4[c];
                acc += (v.x + v.y) + (v.z + v.w);
            }
        } else {
            const int   kw = ker_ws[y];
            const float ev = edge_vals[y];

            if (__popcll(mask) == 1) {
                // Single fixation on this row: visit its kw columns directly.
                const int left = sxs[base + i] - (kw >> 1);
                for (int off = l; off < kw; off += 32) {
                    int c = (left + off) % W;
                    if (c < 0) c += W;
                    float v = (off == 0 || off == kw - 1) ? ev : 1.0f;
                    acc += v * row[c];
                }
            } else {
                // Rare: replay matched fixations across the row in scan order.
                for (int c = l; c < W; c += 32) {
                    float v = 0.0f;
                    unsigned long long m = mask;
                    while (m) {
                        int n = __ffsll(m) - 1;  // ascending n = scan order
                        m &= m - 1;
                        int left = sxs[base + n] - (kw >> 1);
                        int off = (c - left) % W;
                        if (off < 0) off += W;
                        if (off < kw)
                            v = (off == 0 || off == kw - 1) ? ev : 1.0f;
                    }
                    acc += v * row[c];
                }
            }
        }
    }

    // Warp reduce, then block reduce across 32 warps.
    #pragma unroll
    for (int s = 16; s > 0; s >>= 1)
        acc += __shfl_down_sync(0xffffffffu, acc, s);
    if (l == 0) swarp[warp] = acc;
    __syncthreads();

    if (warp == 0) {
        float v = swarp[l];
        #pragma unroll
        for (int s = 16; s > 0; s >>= 1)
            v += __shfl_down_sync(0xffffffffu, v, s);
        if (l == 0)
            d_out[0] = v * (1.0f / ((float)N * (float)B));
    }
}

extern "C" void kernel_launch(void* const* d_in, const int* in_sizes, int n_in,
                              void* d_out, int out_size) {
    const float* y_pred    = (const float*)d_in[0];
    const float* fixations = (const float*)d_in[1];
    const float* edge_vals = (const float*)d_in[2];
    const int*   ker_ws    = (const int*)d_in[3];

    spherical_nss_kernel<<<1, THREADS>>>(y_pred, fixations, edge_vals, ker_ws,
                                         (float*)d_out);
}

// round 4
// speedup vs baseline: 2.0612x; 2.0612x over previous
#include <cuda_runtime.h>

#define H 1024
#define W 2048
#define B 8
#define N 64
#define NTASK (B * N)   // 512
#define FULL 0xffffffffu

__device__ float    g_partial = 0.0f;
__device__ unsigned g_count   = 0u;

// Grid (N, B), one warp per block, ONE launch. Block (i, b) owns the row hit
// by fixation i of batch b iff i is the first fixation of that batch hitting
// the row (ballot dedup). fm is zero outside fixation windows, so the dot
// product visits only covered columns. Final reduction via last-block-done:
// partials atomicAdd into g_partial; the 512th block to finish reads+resets
// it (atomicExch keeps the kernel replay-deterministic) and writes d_out.
__global__ void __launch_bounds__(32)
spherical_nss_kernel(const float* __restrict__ y_pred,
                     const float* __restrict__ fixations,
                     const float* __restrict__ edge_vals,
                     const int*   __restrict__ ker_ws,
                     float* __restrict__ d_out) {
    const int b = blockIdx.y;
    const int i = blockIdx.x;
    const int l = threadIdx.x;

    // Each lane rounds 2 fixations of batch b (rintf == jnp.rint).
    const float2* fx = (const float2*)fixations + b * N;
    float2 f0 = fx[l];
    float2 f1 = fx[l + 32];
    int x0 = (int)rintf(f0.x * (float)(W - 1));
    int y0 = (int)rintf(f0.y * (float)(H - 1));
    int x1 = (int)rintf(f1.x * (float)(W - 1));
    int y1 = (int)rintf(f1.y * (float)(H - 1));

    // This task's (x, y) via shuffle (no shared memory).
    int yi = (i < 32) ? __shfl_sync(FULL, y0, i) : __shfl_sync(FULL, y1, i - 32);
    int xi = (i < 32) ? __shfl_sync(FULL, x0, i) : __shfl_sync(FULL, x1, i - 32);

    // 64-bit mask of fixations in this batch hitting row yi.
    unsigned lo = __ballot_sync(FULL, y0 == yi);
    unsigned hi = __ballot_sync(FULL, y1 == yi);
    unsigned long long mask =
        ((unsigned long long)hi << 32) | (unsigned long long)lo;

    float acc = 0.0f;
    const bool active = !(i > 0 && (mask & ((1ull << i) - 1ull)));

    if (active) {
        const float* row = y_pred + ((size_t)b * H + yi) * W;

        if (yi == 0 || yi == H - 1) {
            // Pole: entire row forced to 1.0 -> vectorized row sum.
            const float4* row4 = (const float4*)row;
            #pragma unroll 4
            for (int c = l; c < W / 4; c += 32) {
                float4 v = row4[c];
                acc += (v.x + v.y) + (v.z + v.w);
            }
        } else {
            const int   kw = __ldg(&ker_ws[yi]);
            const float ev = __ldg(&edge_vals[yi]);

            if (__popcll(mask) == 1) {
                // Single fixation on this row: visit its kw columns directly.
                const int left = xi - (kw >> 1);
                for (int off = l; off < kw; off += 32) {
                    int c = (left + off) % W;
                    if (c < 0) c += W;
                    float v = (off == 0 || off == kw - 1) ? ev : 1.0f;
                    acc += v * row[c];
                }
            } else {
                // Rare: replay matched fixations across the row in scan order.
                for (int c = l; c < W; c += 32) {
                    float v = 0.0f;
                    unsigned long long m = mask;
                    while (m) {
                        int n = __ffsll(m) - 1;   // ascending n = scan order
                        m &= m - 1;
                        int xn = (n < 32) ? __shfl_sync(FULL, x0, n)
                                          : __shfl_sync(FULL, x1, n - 32);
                        int left = xn - (kw >> 1);
                        int off = (c - left) % W;
                        if (off < 0) off += W;
                        if (off < kw)
                            v = (off == 0 || off == kw - 1) ? ev : 1.0f;
                    }
                    acc += v * row[c];
                }
            }
        }
    }

    // Warp reduce.
    #pragma unroll
    for (int s = 16; s > 0; s >>= 1)
        acc += __shfl_down_sync(FULL, acc, s);

    if (l == 0) {
        if (acc != 0.0f) atomicAdd(&g_partial, acc);
        __threadfence();
        unsigned t = atomicAdd(&g_count, 1u);
        if (t == NTASK - 1) {
            // Last block: read+reset scratch (replay-deterministic), write out.
            float total = atomicExch(&g_partial, 0.0f);
            d_out[0] = total * (1.0f / ((float)N * (float)B));
            atomicExch(&g_count, 0u);
        }
    }
}

extern "C" void kernel_launch(void* const* d_in, const int* in_sizes, int n_in,
                              void* d_out, int out_size) {
    const float* y_pred    = (const float*)d_in[0];
    const float* fixations = (const float*)d_in[1];
    const float* edge_vals = (const float*)d_in[2];
    const int*   ker_ws    = (const int*)d_in[3];

    dim3 grid(N, B);
    spherical_nss_kernel<<<grid, 32>>>(y_pred, fixations, edge_vals, ker_ws,
                                       (float*)d_out);
}

// round 6
// speedup vs baseline: 6.7054x; 3.2531x over previous
#include <cuda_runtime.h>

#define H 1024
#define W 2048
#define B 8
#define N 64
#define NTASK (B * N)     // 512
#define WM    (W - 1)     // 2047, power-of-two mod mask
#define FULL  0xffffffffu

// Packed finalize scratch: bits [52..] = block count, bits [0..52) = biased
// fixed-point partial sum (scale 2^24, bias 2^40 per block). One atomicAdd
// per block; same-address total order makes the count==512 observer see the
// complete sum with no fences. Last block writes d_out and resets.
__device__ unsigned long long g_pack = 0ull;

#define FP_SCALE 16777216.0f            // 2^24
#define FP_BIAS  (1ll << 40)

__global__ void __launch_bounds__(32)
spherical_nss_kernel(const float* __restrict__ y_pred,
                     const float* __restrict__ fixations,
                     const float* __restrict__ edge_vals,
                     const int*   __restrict__ ker_ws,
                     float* __restrict__ d_out) {
    const int b = blockIdx.y;
    const int i = blockIdx.x;
    const int l = threadIdx.x;

    // Each lane rounds 2 fixations of batch b (rintf == jnp.rint).
    const float2* fx = (const float2*)fixations + b * N;
    float2 f0 = __ldg(&fx[l]);
    float2 f1 = __ldg(&fx[l + 32]);
    int x0 = (int)rintf(f0.x * (float)(W - 1));
    int y0 = (int)rintf(f0.y * (float)(H - 1));
    int x1 = (int)rintf(f1.x * (float)(W - 1));
    int y1 = (int)rintf(f1.y * (float)(H - 1));

    // This task's row via shuffle.
    int yi = (i < 32) ? __shfl_sync(FULL, y0, i) : __shfl_sync(FULL, y1, i - 32);

    // 64-bit mask of fixations in this batch hitting row yi.
    unsigned lo = __ballot_sync(FULL, y0 == yi);
    unsigned hi = __ballot_sync(FULL, y1 == yi);
    unsigned long long mask =
        ((unsigned long long)hi << 32) | (unsigned long long)lo;

    float acc = 0.0f;
    // Dedup: only the first fixation index hitting this row processes it.
    if (!(i > 0 && (mask & ((1ull << i) - 1ull)))) {
        const float* row = y_pred + ((size_t)b * H + yi) * W;

        if (yi == 0 || yi == H - 1) {
            // Pole: whole row forced to 1.0 -> fully unrolled vector sum.
            const float4* row4 = (const float4*)row;
            #pragma unroll
            for (int k = 0; k < W / 4 / 32; ++k) {
                float4 v = __ldg(&row4[l + 32 * k]);
                acc += (v.x + v.y) + (v.z + v.w);
            }
        } else {
            const int   kw  = __ldg(&ker_ws[yi]);
            const float ev  = __ldg(&edge_vals[yi]);
            const int   cnt = __popcll(mask);

            if (cnt <= 4) {
                // Gather matched lefts in ascending fixation order (scan order).
                int mlefts[4];
                unsigned long long mm = mask;
                #pragma unroll
                for (int j = 0; j < 4; ++j) {
                    int n = __ffsll(mm) - 1;   // garbage when j >= cnt (unused)
                    mm &= mm - 1;
                    int xn = (n < 32) ? __shfl_sync(FULL, x0, n)
                                      : __shfl_sync(FULL, x1, n & 31);
                    mlefts[j] = xn - (kw >> 1);
                }
                // Column c's final value comes from the LAST matched fixation
                // covering it; assign each covered column to that fixation.
                #pragma unroll
                for (int j = 0; j < 4; ++j) {
                    if (j >= cnt) break;
                    const int left = mlefts[j];
                    for (int off = l; off < kw; off += 32) {
                        int c = (left + off) & WM;
                        bool covered_later = false;
                        #pragma unroll
                        for (int j2 = j + 1; j2 < 4; ++j2) {
                            if (j2 < cnt) {
                                int o2 = (c - mlefts[j2]) & WM;
                                covered_later |= (o2 < kw);
                            }
                        }
                        if (!covered_later) {
                            float v = (off == 0 || off == kw - 1) ? ev : 1.0f;
                            acc += v * __ldg(&row[c]);
                        }
                    }
                }
            } else {
                // Vanishingly rare: full-width replay in scan order.
                for (int c = l; c < W; c += 32) {
                    float v = 0.0f;
                    unsigned long long m = mask;
                    while (m) {
                        int n = __ffsll(m) - 1;
                        m &= m - 1;
                        int xn = (n < 32) ? __shfl_sync(FULL, x0, n)
                                          : __shfl_sync(FULL, x1, n & 31);
                        int off = (c - (xn - (kw >> 1))) & WM;
                        if (off < kw)
                            v = (off == 0 || off == kw - 1) ? ev : 1.0f;
                    }
                    acc += v * __ldg(&row[c]);
                }
            }
        }
    }

    // Warp reduce.
    #pragma unroll
    for (int s = 16; s > 0; s >>= 1)
        acc += __shfl_down_sync(FULL, acc, s);

    if (l == 0) {
        // Single packed atomic: count in bits [52..], biased fixed-point sum
        // below. No fence needed: same-address RMW total order.
        long long fixedv = __float2ll_rn(acc * FP_SCALE) + FP_BIAS;
        unsigned long long pack =
            (1ull << 52) | (unsigned long long)fixedv;
        unsigned long long old = atomicAdd(&g_pack, pack);
        if ((old >> 52) == NTASK - 1) {
            unsigned long long tot = old + pack;
            long long sum_fixed =
                (long long)(tot & ((1ull << 52) - 1ull)) -
                (long long)NTASK * FP_BIAS;
            float total = (float)sum_fixed * (1.0f / FP_SCALE);
            d_out[0] = total * (1.0f / ((float)N * (float)B));
            atomicExch(&g_pack, 0ull);   // reset for next graph replay
        }
    }
}

extern "C" void kernel_launch(void* const* d_in, const int* in_sizes, int n_in,
                              void* d_out, int out_size) {
    const float* y_pred    = (const float*)d_in[0];
    const float* fixations = (const float*)d_in[1];
    const float* edge_vals = (const float*)d_in[2];
    const int*   ker_ws    = (const int*)d_in[3];

    dim3 grid(N, B);
    spherical_nss_kernel<<<grid, 32>>>(y_pred, fixations, edge_vals, ker_ws,
                                       (float*)d_out);
}